// round 12
// baseline (speedup 1.0000x reference)
#include <cuda_runtime.h>
#include <cuda_fp16.h>
#include <math.h>

#define NN 100000
#define DD 128
#define EE 600000
#define HH 8
#define NB ((NN + 1023) / 1024)

#define PADH 136   // half pitch: frag bank = 4g+tg (conflict-free)

// ---------------- scratch (device globals) ------------------------------------
__device__ __align__(16) __half g_Qh[NN * DD];
__device__ __align__(16) __half g_Kh[NN * DD];
__device__ __align__(16) __half g_Vh[NN * DD];
__device__ __align__(16) __half g_Zh[NN * DD];       // residual, then +aggr (fp16)
__device__ __align__(16) __half g_Wt[6][128 * PADH]; // transposed fp16 weights
__device__ __align__(16) float g_scores[EE * HH];    // exp(score), CSR order
__device__ float g_ssum[NN * HH];
__device__ __align__(16) float g_eaq[DD];
__device__ __align__(16) float g_eak[DD];
__device__ int g_src[EE];
__device__ int g_dst[EE];
__device__ int g_esrc[EE];   // src id per CSR slot
__device__ int g_deg[NN];
__device__ int g_off[NN + 1];
__device__ int g_cur[NN];
__device__ int g_bsum[NB];
__device__ int g_boff[NB];
__device__ int g_is64;

// ---------------- helpers ----------------------------------------------------
__device__ __forceinline__ void mma_f16(float* c, const unsigned* a, const unsigned* b) {
    asm volatile(
        "mma.sync.aligned.m16n8k16.row.col.f32.f16.f16.f32 "
        "{%0,%1,%2,%3}, {%4,%5,%6,%7}, {%8,%9}, {%0,%1,%2,%3};"
        : "+f"(c[0]), "+f"(c[1]), "+f"(c[2]), "+f"(c[3])
        : "r"(a[0]), "r"(a[1]), "r"(a[2]), "r"(a[3]), "r"(b[0]), "r"(b[1]));
}
__device__ __forceinline__ void cp16h(__half* smem_dst, const __half* gsrc) {
    unsigned s = (unsigned)__cvta_generic_to_shared(smem_dst);
    asm volatile("cp.async.cg.shared.global [%0], [%1], 16;" :: "r"(s), "l"(gsrc));
}
#define CP_COMMIT() asm volatile("cp.async.commit_group;")
#define CP_WAIT(n)  asm volatile("cp.async.wait_group %0;" :: "n"(n))

// 8-half dot in fp32
__device__ __forceinline__ float dot8(uint4 a, uint4 b) {
    float2 a0 = __half22float2(*(__half2*)&a.x);
    float2 a1 = __half22float2(*(__half2*)&a.y);
    float2 a2 = __half22float2(*(__half2*)&a.z);
    float2 a3 = __half22float2(*(__half2*)&a.w);
    float2 b0 = __half22float2(*(__half2*)&b.x);
    float2 b1 = __half22float2(*(__half2*)&b.y);
    float2 b2 = __half22float2(*(__half2*)&b.z);
    float2 b3 = __half22float2(*(__half2*)&b.w);
    float p = a0.x * b0.x;
    p = fmaf(a0.y, b0.y, p);
    p = fmaf(a1.x, b1.x, p);
    p = fmaf(a1.y, b1.y, p);
    p = fmaf(a2.x, b2.x, p);
    p = fmaf(a2.y, b2.y, p);
    p = fmaf(a3.x, b3.x, p);
    p = fmaf(a3.y, b3.y, p);
    return p;
}

// ---------------- transpose all 6 weights once: [k][n] f32 -> [n][k] f16 -------
__global__ void k_wt(const float* __restrict__ qW,  const float* __restrict__ kW,
                     const float* __restrict__ vW,  const float* __restrict__ resW,
                     const float* __restrict__ oW1, const float* __restrict__ oW2) {
    const float* W;
    switch (blockIdx.x) {
        case 0: W = qW; break;
        case 1: W = kW; break;
        case 2: W = vW; break;
        case 3: W = resW; break;
        case 4: W = oW1; break;
        default: W = oW2; break;
    }
    __half* dst = g_Wt[blockIdx.x];
    for (int task = threadIdx.x; task < 128 * 8; task += 256) {
        int n = task & 127, kg = task >> 7;
        float w[16];
        #pragma unroll
        for (int k = 0; k < 16; ++k) w[k] = W[(kg * 16 + k) * 128 + n];
        uint4 u0, u1;
        __half2 p;
        p = __floats2half2_rn(w[0],  w[1]);  u0.x = *(unsigned*)&p;
        p = __floats2half2_rn(w[2],  w[3]);  u0.y = *(unsigned*)&p;
        p = __floats2half2_rn(w[4],  w[5]);  u0.z = *(unsigned*)&p;
        p = __floats2half2_rn(w[6],  w[7]);  u0.w = *(unsigned*)&p;
        p = __floats2half2_rn(w[8],  w[9]);  u1.x = *(unsigned*)&p;
        p = __floats2half2_rn(w[10], w[11]); u1.y = *(unsigned*)&p;
        p = __floats2half2_rn(w[12], w[13]); u1.z = *(unsigned*)&p;
        p = __floats2half2_rn(w[14], w[15]); u1.w = *(unsigned*)&p;
        *(uint4*)(dst + n * PADH + kg * 16)     = u0;
        *(uint4*)(dst + n * PADH + kg * 16 + 8) = u1;
    }
}

// ---------------- dtype detect + deg zero -------------------------------------
__global__ void k_detect(const int* __restrict__ w) {
    int i = blockIdx.x * 256 + threadIdx.x;
    if (i < NN) g_deg[i] = 0;
    if (blockIdx.x == 0) {
        __shared__ int red[256];
        int acc = 0;
        for (int k = threadIdx.x; k < 4096; k += 256) acc |= w[2 * k + 1];
        red[threadIdx.x] = acc;
        __syncthreads();
        for (int s = 128; s > 0; s >>= 1) {
            if (threadIdx.x < s) red[threadIdx.x] |= red[threadIdx.x + s];
            __syncthreads();
        }
        if (threadIdx.x == 0) g_is64 = (red[0] == 0) ? 1 : 0;
    }
}

// ---------------- index conversion + dst histogram -----------------------------
__global__ void k_cvt(const void* __restrict__ ei) {
    int e = blockIdx.x * blockDim.x + threadIdx.x;
    if (e >= EE) return;
    int s, d;
    if (g_is64) {
        const long long* p = (const long long*)ei;
        s = (int)p[e];
        d = (int)p[EE + e];
    } else {
        const int* p = (const int*)ei;
        s = p[e];
        d = p[EE + e];
    }
    g_src[e] = s;
    g_dst[e] = d;
    atomicAdd(&g_deg[d], 1);
}

// ---------------- CSR build ----------------------------------------------------
__global__ void k_scan1() {
    __shared__ int s[1024];
    int t = threadIdx.x;
    int i = blockIdx.x * 1024 + t;
    int v = (i < NN) ? g_deg[i] : 0;
    s[t] = v;
    __syncthreads();
    #pragma unroll
    for (int d = 1; d < 1024; d <<= 1) {
        int x = (t >= d) ? s[t - d] : 0;
        __syncthreads();
        s[t] += x;
        __syncthreads();
    }
    if (i < NN) g_off[i] = s[t] - v;
    if (t == 1023) g_bsum[blockIdx.x] = s[1023];
}
__global__ void k_scan2() {
    if (threadIdx.x == 0) {
        int run = 0;
        for (int b = 0; b < NB; ++b) {
            g_boff[b] = run;
            run += g_bsum[b];
        }
        g_off[NN] = run;
    }
}
__global__ void k_scan3() {
    int i = blockIdx.x * blockDim.x + threadIdx.x;
    if (i < NN) {
        int v = g_off[i] + g_boff[i >> 10];
        g_off[i] = v;
        g_cur[i] = v;
        #pragma unroll
        for (int h = 0; h < HH; ++h) g_ssum[i * HH + h] = 0.f;
    }
}
__global__ void k_scatter() {
    int e = blockIdx.x * blockDim.x + threadIdx.x;
    if (e >= EE) return;
    int pos = atomicAdd(&g_cur[g_dst[e]], 1);
    g_esrc[pos] = g_src[e];
}

// ---------------- tiny edge-attr MLP ------------------------------------------
__global__ void k_ea(const float* __restrict__ nt, const float* __restrict__ et,
                     const float* __restrict__ mW1, const float* __restrict__ mb1,
                     const float* __restrict__ m_g, const float* __restrict__ m_b,
                     const float* __restrict__ m_m, const float* __restrict__ m_v,
                     const float* __restrict__ mW2, const float* __restrict__ mb2,
                     const float* __restrict__ qW,  const float* __restrict__ qb,
                     const float* __restrict__ kW,  const float* __restrict__ kb) {
    __shared__ float merged[2 * DD];
    __shared__ float h[DD];
    __shared__ float ea[DD];
    int t = threadIdx.x;  // 128 threads
    merged[t]      = nt[t];
    merged[t + DD] = et[t];
    __syncthreads();
    float s = mb1[t];
    for (int i = 0; i < 2 * DD; ++i) s = fmaf(merged[i], mW1[i * DD + t], s);
    float bn = (s - m_m[t]) * rsqrtf(m_v[t] + 1e-5f) * m_g[t] + m_b[t];
    h[t] = fmaxf(bn, 0.f);
    __syncthreads();
    float s2 = mb2[t];
    for (int i = 0; i < DD; ++i) s2 = fmaf(h[i], mW2[i * DD + t], s2);
    ea[t] = s2;
    __syncthreads();
    float sq = qb[t], sk = kb[t];
    for (int i = 0; i < DD; ++i) {
        sq = fmaf(ea[i], qW[i * DD + t], sq);
        sk = fmaf(ea[i], kW[i * DD + t], sk);
    }
    g_eaq[t] = sq;
    g_eak[t] = sk;
}

// ---------------- GEMM building blocks -----------------------------------------
__device__ __forceinline__ void stage_A64(__half* As, const float* src, int row0, int t) {
    for (int task = t; task < 1024; task += 256) {
        int r = task >> 4, q = task & 15;
        int gr = row0 + r;
        float4 v0 = make_float4(0.f, 0.f, 0.f, 0.f), v1 = v0;
        if (gr < NN) {
            v0 = *(const float4*)(src + (size_t)gr * DD + q * 8);
            v1 = *(const float4*)(src + (size_t)gr * DD + q * 8 + 4);
        }
        __half2 h0 = __floats2half2_rn(v0.x, v0.y);
        __half2 h1 = __floats2half2_rn(v0.z, v0.w);
        __half2 h2 = __floats2half2_rn(v1.x, v1.y);
        __half2 h3 = __floats2half2_rn(v1.z, v1.w);
        uint4 u;
        u.x = *(unsigned*)&h0; u.y = *(unsigned*)&h1;
        u.z = *(unsigned*)&h2; u.w = *(unsigned*)&h3;
        *(uint4*)(As + r * PADH + q * 8) = u;
    }
}
__device__ __forceinline__ void stage_A64h(__half* As, const __half* src, int row0, int t) {
    for (int task = t; task < 1024; task += 256) {
        int r = task >> 4, q = task & 15;
        int gr = row0 + r;
        __half* dst = As + r * PADH + q * 8;
        if (gr < NN) cp16h(dst, src + (size_t)gr * DD + q * 8);
        else *(uint4*)dst = make_uint4(0, 0, 0, 0);
    }
    CP_COMMIT();
}
__device__ __forceinline__ void cp_Wh(__half* Wh, const __half* src, int t) {
    for (int i = t * 8; i < 128 * PADH; i += 2048) cp16h(Wh + i, src + i);
    CP_COMMIT();
}
__device__ __forceinline__ void gemm_main(float acc[2][4][4], const __half* As,
                                          const __half* Wh, int wm, int wn,
                                          int g, int tg) {
    #pragma unroll
    for (int mt = 0; mt < 2; ++mt)
        #pragma unroll
        for (int nt = 0; nt < 4; ++nt)
            #pragma unroll
            for (int j = 0; j < 4; ++j) acc[mt][nt][j] = 0.f;

    const __half* Ab = As + (wm * 32 + g) * PADH + 2 * tg;
    const __half* Bb = Wh + (wn * 32 + g) * PADH + 2 * tg;

    #pragma unroll
    for (int kk = 0; kk < 8; ++kk) {
        unsigned a[2][4], b[4][2];
        #pragma unroll
        for (int mt = 0; mt < 2; ++mt) {
            const __half* p = Ab + mt * 16 * PADH + kk * 16;
            a[mt][0] = *(const unsigned*)(p);
            a[mt][1] = *(const unsigned*)(p + 8 * PADH);
            a[mt][2] = *(const unsigned*)(p + 8);
            a[mt][3] = *(const unsigned*)(p + 8 * PADH + 8);
        }
        #pragma unroll
        for (int nt = 0; nt < 4; ++nt) {
            const __half* p = Bb + nt * 8 * PADH + kk * 16;
            b[nt][0] = *(const unsigned*)(p);
            b[nt][1] = *(const unsigned*)(p + 8);
        }
        #pragma unroll
        for (int mt = 0; mt < 2; ++mt)
            #pragma unroll
            for (int nt = 0; nt < 4; ++nt)
                mma_f16(acc[mt][nt], a[mt], b[nt]);
    }
}

#define ASZ64 (64 * PADH * 2)
#define WHZ   (128 * PADH * 2)

// ---------------- node projection GEMM (double-buffered Wh, 2 CTAs/SM) ---------
__global__ __launch_bounds__(256, 2)
void k_proj(const float* __restrict__ x, const float* __restrict__ vb) {
    extern __shared__ char smc[];
    __half* As  = (__half*)smc;                    // [64][PADH]
    __half* Wb0 = (__half*)(smc + ASZ64);          // [128][PADH]
    __half* Wb1 = (__half*)(smc + ASZ64 + WHZ);    // [128][PADH]
    const int t = threadIdx.x;
    const int warp = t >> 5, lane = t & 31;
    const int g = lane >> 2, tg = lane & 3;
    const int wm = warp >> 2, wn = warp & 3;
    const int row0 = blockIdx.x * 64;

    cp_Wh(Wb0, g_Wt[0], t);
    stage_A64(As, x, row0, t);
    CP_WAIT(0);
    __syncthreads();

    __half* Og[4] = {g_Qh, g_Kh, g_Vh, g_Zh};

    for (int w = 0; w < 4; ++w) {
        __half* Wc = (w & 1) ? Wb1 : Wb0;
        __half* Wn = (w & 1) ? Wb0 : Wb1;
        if (w < 3) cp_Wh(Wn, g_Wt[w + 1], t);   // prefetch overlaps GEMM + epilogue

        float acc[2][4][4];
        gemm_main(acc, As, Wc, wm, wn, g, tg);

        __half* O = Og[w];
        #pragma unroll
        for (int mt = 0; mt < 2; ++mt) {
            int r = row0 + wm * 32 + mt * 16 + g;
            #pragma unroll
            for (int nt = 0; nt < 4; ++nt) {
                int c = wn * 32 + nt * 8 + tg * 2;
                float bv0 = 0.f, bv1 = 0.f;
                if (w == 0) { bv0 = g_eaq[c]; bv1 = g_eaq[c + 1]; }
                else if (w == 1) { bv0 = g_eak[c]; bv1 = g_eak[c + 1]; }
                else if (w == 2) { bv0 = vb[c]; bv1 = vb[c + 1]; }
                if (r < NN)
                    *(__half2*)(O + (size_t)r * DD + c) =
                        __floats2half2_rn(acc[mt][nt][0] + bv0, acc[mt][nt][1] + bv1);
                if (r + 8 < NN)
                    *(__half2*)(O + (size_t)(r + 8) * DD + c) =
                        __floats2half2_rn(acc[mt][nt][2] + bv0, acc[mt][nt][3] + bv1);
            }
        }
        if (w < 3) {
            CP_WAIT(0);
            __syncthreads();   // next buffer visible; Wc safe (all reads done)
        }
    }
}

// ---------------- edge pass 1 (CSR, lane-per-head, 4 edges in flight) ----------
__global__ __launch_bounds__(256, 1)
void k_scores() {
    int n = blockIdx.x * 8 + (threadIdx.x >> 5);
    int lane = threadIdx.x & 31;
    if (n >= NN) return;
    int beg = g_off[n], end = g_off[n + 1];
    if (beg == end) return;
    int el = lane >> 3;     // edge slot 0..3
    int h  = lane & 7;      // head

    // K for head h of node n (16 halves)
    uint4 ka = *(const uint4*)(g_Kh + (size_t)n * DD + h * 16);
    uint4 kb = *(const uint4*)(g_Kh + (size_t)n * DD + h * 16 + 8);

    for (int i = beg; i < end; i += 4) {
        int idx = i + el;
        bool act = idx < end;
        int s = g_esrc[act ? idx : beg];
        uint4 qa = *(const uint4*)(g_Qh + (size_t)s * DD + h * 16);
        uint4 qb = *(const uint4*)(g_Qh + (size_t)s * DD + h * 16 + 8);
        float p = dot8(qa, ka) + dot8(qb, kb);
        if (act) {
            float ex = expf(p * 0.25f);   // 1/sqrt(DH=16); |s| small -> no shift
            g_scores[(size_t)idx * HH + h] = ex;
            atomicAdd(&g_ssum[s * HH + h], ex);
        }
    }
}

// ---------------- edge pass 2 (CSR order, 2-edge unroll): warp per dst ---------
__global__ __launch_bounds__(256, 1)
void k_aggr() {
    int n = blockIdx.x * 8 + (threadIdx.x >> 5);
    int lane = threadIdx.x & 31;
    if (n >= NN) return;
    int beg = g_off[n], end = g_off[n + 1];
    int h = lane >> 2;
    uint2 zu = *(const uint2*)(g_Zh + (size_t)n * DD + lane * 4);  // residual f16
    float2 z0 = __half22float2(*(__half2*)&zu.x);
    float2 z1 = __half22float2(*(__half2*)&zu.y);
    float4 acc = make_float4(z0.x, z0.y, z1.x, z1.y);
    for (int i = beg; i < end; i += 2) {
        bool two = (i + 1 < end);
        int s0 = g_esrc[i];
        int s1 = two ? g_esrc[i + 1] : s0;
        float e0 = g_scores[(size_t)i * HH + h];
        float e1 = two ? g_scores[(size_t)(i + 1) * HH + h] : 0.f;
        uint2 va = *(const uint2*)(g_Vh + (size_t)s0 * DD + lane * 4);
        uint2 vb = *(const uint2*)(g_Vh + (size_t)s1 * DD + lane * 4);
        float al0 = __fdividef(e0, g_ssum[s0 * HH + h]);
        float al1 = two ? __fdividef(e1, g_ssum[s1 * HH + h]) : 0.f;
        float2 a0 = __half22float2(*(__half2*)&va.x);
        float2 a1 = __half22float2(*(__half2*)&va.y);
        float2 c0 = __half22float2(*(__half2*)&vb.x);
        float2 c1 = __half22float2(*(__half2*)&vb.y);
        acc.x = fmaf(a0.x, al0, fmaf(c0.x, al1, acc.x));
        acc.y = fmaf(a0.y, al0, fmaf(c0.y, al1, acc.y));
        acc.z = fmaf(a1.x, al0, fmaf(c1.x, al1, acc.z));
        acc.w = fmaf(a1.y, al0, fmaf(c1.y, al1, acc.w));
    }
    __half2 o0 = __floats2half2_rn(acc.x, acc.y);
    __half2 o1 = __floats2half2_rn(acc.z, acc.w);
    uint2 ou;
    ou.x = *(unsigned*)&o0;
    ou.y = *(unsigned*)&o1;
    *(uint2*)(g_Zh + (size_t)n * DD + lane * 4) = ou;
}

// ---------------- fused output MLP (double-buffered Wh, 2 CTAs/SM) -------------
__global__ __launch_bounds__(256, 2)
void k_out(const float* __restrict__ ob1,
           const float* __restrict__ o_g, const float* __restrict__ o_b,
           const float* __restrict__ o_m, const float* __restrict__ o_v,
           const float* __restrict__ ob2, float* __restrict__ out) {
    extern __shared__ char smc[];
    __half* As  = (__half*)smc;                    // [64][PADH]
    __half* Wb0 = (__half*)(smc + ASZ64);          // [128][PADH]
    __half* Wb1 = (__half*)(smc + ASZ64 + WHZ);    // [128][PADH]
    float*  bnS = (float*)(smc + ASZ64 + 2 * WHZ); // sc[128], sh[128], b1[128]
    const int t = threadIdx.x;
    const int warp = t >> 5, lane = t & 31;
    const int g = lane >> 2, tg = lane & 3;
    const int wm = warp >> 2, wn = warp & 3;
    const int row0 = blockIdx.x * 64;

    cp_Wh(Wb0, g_Wt[4], t);
    cp_Wh(Wb1, g_Wt[5], t);
    stage_A64h(As, g_Zh, row0, t);
    if (t < 128) {
        float sc = o_g[t] * rsqrtf(o_v[t] + 1e-5f);
        bnS[t]       = sc;
        bnS[128 + t] = o_b[t] - o_m[t] * sc;
        bnS[256 + t] = ob1[t];
    }
    CP_WAIT(0);
    __syncthreads();

    float acc[2][4][4];
    gemm_main(acc, As, Wb0, wm, wn, g, tg);
    __syncthreads();   // all As reads done before rewrite

    // BN + leakyReLU on fragments, re-stage Y (fp16) into As
    #pragma unroll
    for (int mt = 0; mt < 2; ++mt) {
        int rl = wm * 32 + mt * 16 + g;
        #pragma unroll
        for (int nt = 0; nt < 4; ++nt) {
            int c = wn * 32 + nt * 8 + tg * 2;
            float sc0 = bnS[c],       sc1 = bnS[c + 1];
            float sh0 = bnS[128 + c], sh1 = bnS[129 + c];
            float b10 = bnS[256 + c], b11 = bnS[257 + c];
            float y0 = (acc[mt][nt][0] + b10) * sc0 + sh0;
            float y1 = (acc[mt][nt][1] + b11) * sc1 + sh1;
            float y2 = (acc[mt][nt][2] + b10) * sc0 + sh0;
            float y3 = (acc[mt][nt][3] + b11) * sc1 + sh1;
            y0 = (y0 > 0.f) ? y0 : 0.01f * y0;
            y1 = (y1 > 0.f) ? y1 : 0.01f * y1;
            y2 = (y2 > 0.f) ? y2 : 0.01f * y2;
            y3 = (y3 > 0.f) ? y3 : 0.01f * y3;
            *(__half2*)(As + rl * PADH + c)       = __floats2half2_rn(y0, y1);
            *(__half2*)(As + (rl + 8) * PADH + c) = __floats2half2_rn(y2, y3);
        }
    }
    __syncthreads();

    gemm_main(acc, As, Wb1, wm, wn, g, tg);

    #pragma unroll
    for (int mt = 0; mt < 2; ++mt) {
        int r = row0 + wm * 32 + mt * 16 + g;
        #pragma unroll
        for (int nt = 0; nt < 4; ++nt) {
            int c = wn * 32 + nt * 8 + tg * 2;
            float b20 = ob2[c], b21 = ob2[c + 1];
            if (r < NN)
                *(float2*)(out + (size_t)r * DD + c) =
                    make_float2(acc[mt][nt][0] + b20, acc[mt][nt][1] + b21);
            if (r + 8 < NN)
                *(float2*)(out + (size_t)(r + 8) * DD + c) =
                    make_float2(acc[mt][nt][2] + b20, acc[mt][nt][3] + b21);
        }
    }
}

// ---------------- launch ------------------------------------------------------
extern "C" void kernel_launch(void* const* d_in, const int* in_sizes, int n_in,
                              void* d_out, int out_size) {
    const float* x    = (const float*)d_in[0];
    const void*  ei   = d_in[1];
    const float* nt   = (const float*)d_in[2];
    const float* et   = (const float*)d_in[3];
    const float* mW1  = (const float*)d_in[4];
    const float* mb1  = (const float*)d_in[5];
    const float* m_g  = (const float*)d_in[6];
    const float* m_b  = (const float*)d_in[7];
    const float* m_m  = (const float*)d_in[8];
    const float* m_v  = (const float*)d_in[9];
    const float* mW2  = (const float*)d_in[10];
    const float* mb2  = (const float*)d_in[11];
    const float* resW = (const float*)d_in[12];
    const float* qW   = (const float*)d_in[13];
    const float* qb   = (const float*)d_in[14];
    const float* kW   = (const float*)d_in[15];
    const float* kb   = (const float*)d_in[16];
    const float* vW   = (const float*)d_in[17];
    const float* vb   = (const float*)d_in[18];
    const float* oW1  = (const float*)d_in[19];
    const float* ob1  = (const float*)d_in[20];
    const float* o_g  = (const float*)d_in[21];
    const float* o_b  = (const float*)d_in[22];
    const float* o_m  = (const float*)d_in[23];
    const float* o_v  = (const float*)d_in[24];
    const float* oW2  = (const float*)d_in[25];
    const float* ob2  = (const float*)d_in[26];
    float* out = (float*)d_out;

    const int SMEM_P = ASZ64 + 2 * WHZ;                      // 87040 B
    const int SMEM_O = SMEM_P + 3 * 128 * (int)sizeof(float);
    cudaFuncSetAttribute(k_proj, cudaFuncAttributeMaxDynamicSharedMemorySize, SMEM_P);
    cudaFuncSetAttribute(k_out,  cudaFuncAttributeMaxDynamicSharedMemorySize, SMEM_O);

    k_wt<<<6, 256>>>(qW, kW, vW, resW, oW1, oW2);
    k_ea<<<1, 128>>>(nt, et, mW1, mb1, m_g, m_b, m_m, m_v, mW2, mb2, qW, qb, kW, kb);
    k_detect<<<(NN + 255) / 256, 256>>>((const int*)ei);
    k_proj<<<(NN + 63) / 64, 256, SMEM_P>>>(x, vb);       // ncu idx 3
    k_cvt<<<(EE + 255) / 256, 256>>>(ei);
    k_scan1<<<NB, 1024>>>();
    k_scan2<<<1, 32>>>();
    k_scan3<<<(NN + 255) / 256, 256>>>();
    k_scatter<<<(EE + 255) / 256, 256>>>();
    k_scores<<<(NN + 7) / 8, 256>>>();
    k_aggr<<<(NN + 7) / 8, 256>>>();
    k_out<<<(NN + 63) / 64, 256, SMEM_O>>>(ob1, o_g, o_b, o_m, o_v, ob2, out);
}

// round 13
// speedup vs baseline: 1.0807x; 1.0807x over previous
#include <cuda_runtime.h>
#include <cuda_fp16.h>
#include <math.h>

#define NN 100000
#define DD 128
#define EE 600000
#define HH 8
#define NB ((NN + 1023) / 1024)

#define PADH 136   // half pitch: frag bank = 4g+tg (conflict-free)

// ---------------- scratch (device globals) ------------------------------------
__device__ __align__(16) __half g_Qh[NN * DD];
__device__ __align__(16) __half g_Kh[NN * DD];
__device__ __align__(16) __half g_Vh[NN * DD];
__device__ __align__(16) __half g_Zh[NN * DD];       // residual, then +aggr (fp16)
__device__ __align__(16) __half g_Wt[6][128 * PADH]; // transposed fp16 weights
__device__ __align__(16) float g_scores[EE * HH];    // exp(score), CSR order
__device__ float g_ssum[NN * HH];
__device__ __align__(16) float g_eaq[DD];
__device__ __align__(16) float g_eak[DD];
__device__ int g_src[EE];
__device__ int g_dst[EE];
__device__ int g_esrc[EE];   // src id per CSR slot
__device__ int g_deg[NN];
__device__ int g_off[NN + 1];
__device__ int g_cur[NN];
__device__ int g_bsum[NB];
__device__ int g_boff[NB];
__device__ int g_is64;

// ---------------- helpers ----------------------------------------------------
__device__ __forceinline__ void mma_f16(float* c, const unsigned* a, const unsigned* b) {
    asm volatile(
        "mma.sync.aligned.m16n8k16.row.col.f32.f16.f16.f32 "
        "{%0,%1,%2,%3}, {%4,%5,%6,%7}, {%8,%9}, {%0,%1,%2,%3};"
        : "+f"(c[0]), "+f"(c[1]), "+f"(c[2]), "+f"(c[3])
        : "r"(a[0]), "r"(a[1]), "r"(a[2]), "r"(a[3]), "r"(b[0]), "r"(b[1]));
}
__device__ __forceinline__ void cp16h(__half* smem_dst, const __half* gsrc) {
    unsigned s = (unsigned)__cvta_generic_to_shared(smem_dst);
    asm volatile("cp.async.cg.shared.global [%0], [%1], 16;" :: "r"(s), "l"(gsrc));
}
#define CP_COMMIT() asm volatile("cp.async.commit_group;")
#define CP_WAIT(n)  asm volatile("cp.async.wait_group %0;" :: "n"(n))

// ---------------- transpose all 6 weights once: [k][n] f32 -> [n][k] f16 -------
__global__ void k_wt(const float* __restrict__ qW,  const float* __restrict__ kW,
                     const float* __restrict__ vW,  const float* __restrict__ resW,
                     const float* __restrict__ oW1, const float* __restrict__ oW2) {
    const float* W;
    switch (blockIdx.x) {
        case 0: W = qW; break;
        case 1: W = kW; break;
        case 2: W = vW; break;
        case 3: W = resW; break;
        case 4: W = oW1; break;
        default: W = oW2; break;
    }
    __half* dst = g_Wt[blockIdx.x];
    for (int task = threadIdx.x; task < 128 * 8; task += 256) {
        int n = task & 127, kg = task >> 7;
        float w[16];
        #pragma unroll
        for (int k = 0; k < 16; ++k) w[k] = W[(kg * 16 + k) * 128 + n];
        uint4 u0, u1;
        __half2 p;
        p = __floats2half2_rn(w[0],  w[1]);  u0.x = *(unsigned*)&p;
        p = __floats2half2_rn(w[2],  w[3]);  u0.y = *(unsigned*)&p;
        p = __floats2half2_rn(w[4],  w[5]);  u0.z = *(unsigned*)&p;
        p = __floats2half2_rn(w[6],  w[7]);  u0.w = *(unsigned*)&p;
        p = __floats2half2_rn(w[8],  w[9]);  u1.x = *(unsigned*)&p;
        p = __floats2half2_rn(w[10], w[11]); u1.y = *(unsigned*)&p;
        p = __floats2half2_rn(w[12], w[13]); u1.z = *(unsigned*)&p;
        p = __floats2half2_rn(w[14], w[15]); u1.w = *(unsigned*)&p;
        *(uint4*)(dst + n * PADH + kg * 16)     = u0;
        *(uint4*)(dst + n * PADH + kg * 16 + 8) = u1;
    }
}

// ---------------- dtype detect + deg zero -------------------------------------
__global__ void k_detect(const int* __restrict__ w) {
    int i = blockIdx.x * 256 + threadIdx.x;
    if (i < NN) g_deg[i] = 0;
    if (blockIdx.x == 0) {
        __shared__ int red[256];
        int acc = 0;
        for (int k = threadIdx.x; k < 4096; k += 256) acc |= w[2 * k + 1];
        red[threadIdx.x] = acc;
        __syncthreads();
        for (int s = 128; s > 0; s >>= 1) {
            if (threadIdx.x < s) red[threadIdx.x] |= red[threadIdx.x + s];
            __syncthreads();
        }
        if (threadIdx.x == 0) g_is64 = (red[0] == 0) ? 1 : 0;
    }
}

// ---------------- index conversion + dst histogram -----------------------------
__global__ void k_cvt(const void* __restrict__ ei) {
    int e = blockIdx.x * blockDim.x + threadIdx.x;
    if (e >= EE) return;
    int s, d;
    if (g_is64) {
        const long long* p = (const long long*)ei;
        s = (int)p[e];
        d = (int)p[EE + e];
    } else {
        const int* p = (const int*)ei;
        s = p[e];
        d = p[EE + e];
    }
    g_src[e] = s;
    g_dst[e] = d;
    atomicAdd(&g_deg[d], 1);
}

// ---------------- CSR build ----------------------------------------------------
__global__ void k_scan1() {
    __shared__ int s[1024];
    int t = threadIdx.x;
    int i = blockIdx.x * 1024 + t;
    int v = (i < NN) ? g_deg[i] : 0;
    s[t] = v;
    __syncthreads();
    #pragma unroll
    for (int d = 1; d < 1024; d <<= 1) {
        int x = (t >= d) ? s[t - d] : 0;
        __syncthreads();
        s[t] += x;
        __syncthreads();
    }
    if (i < NN) g_off[i] = s[t] - v;
    if (t == 1023) g_bsum[blockIdx.x] = s[1023];
}
__global__ void k_scan2() {
    if (threadIdx.x == 0) {
        int run = 0;
        for (int b = 0; b < NB; ++b) {
            g_boff[b] = run;
            run += g_bsum[b];
        }
        g_off[NN] = run;
    }
}
__global__ void k_scan3() {
    int i = blockIdx.x * blockDim.x + threadIdx.x;
    if (i < NN) {
        int v = g_off[i] + g_boff[i >> 10];
        g_off[i] = v;
        g_cur[i] = v;
        #pragma unroll
        for (int h = 0; h < HH; ++h) g_ssum[i * HH + h] = 0.f;
    }
}
__global__ void k_scatter() {
    int e = blockIdx.x * blockDim.x + threadIdx.x;
    if (e >= EE) return;
    int pos = atomicAdd(&g_cur[g_dst[e]], 1);
    g_esrc[pos] = g_src[e];
}

// ---------------- tiny edge-attr MLP ------------------------------------------
__global__ void k_ea(const float* __restrict__ nt, const float* __restrict__ et,
                     const float* __restrict__ mW1, const float* __restrict__ mb1,
                     const float* __restrict__ m_g, const float* __restrict__ m_b,
                     const float* __restrict__ m_m, const float* __restrict__ m_v,
                     const float* __restrict__ mW2, const float* __restrict__ mb2,
                     const float* __restrict__ qW,  const float* __restrict__ qb,
                     const float* __restrict__ kW,  const float* __restrict__ kb) {
    __shared__ float merged[2 * DD];
    __shared__ float h[DD];
    __shared__ float ea[DD];
    int t = threadIdx.x;  // 128 threads
    merged[t]      = nt[t];
    merged[t + DD] = et[t];
    __syncthreads();
    float s = mb1[t];
    for (int i = 0; i < 2 * DD; ++i) s = fmaf(merged[i], mW1[i * DD + t], s);
    float bn = (s - m_m[t]) * rsqrtf(m_v[t] + 1e-5f) * m_g[t] + m_b[t];
    h[t] = fmaxf(bn, 0.f);
    __syncthreads();
    float s2 = mb2[t];
    for (int i = 0; i < DD; ++i) s2 = fmaf(h[i], mW2[i * DD + t], s2);
    ea[t] = s2;
    __syncthreads();
    float sq = qb[t], sk = kb[t];
    for (int i = 0; i < DD; ++i) {
        sq = fmaf(ea[i], qW[i * DD + t], sq);
        sk = fmaf(ea[i], kW[i * DD + t], sk);
    }
    g_eaq[t] = sq;
    g_eak[t] = sk;
}

// ---------------- GEMM building blocks -----------------------------------------
__device__ __forceinline__ void stage_A64(__half* As, const float* src, int row0, int t) {
    for (int task = t; task < 1024; task += 256) {
        int r = task >> 4, q = task & 15;
        int gr = row0 + r;
        float4 v0 = make_float4(0.f, 0.f, 0.f, 0.f), v1 = v0;
        if (gr < NN) {
            v0 = *(const float4*)(src + (size_t)gr * DD + q * 8);
            v1 = *(const float4*)(src + (size_t)gr * DD + q * 8 + 4);
        }
        __half2 h0 = __floats2half2_rn(v0.x, v0.y);
        __half2 h1 = __floats2half2_rn(v0.z, v0.w);
        __half2 h2 = __floats2half2_rn(v1.x, v1.y);
        __half2 h3 = __floats2half2_rn(v1.z, v1.w);
        uint4 u;
        u.x = *(unsigned*)&h0; u.y = *(unsigned*)&h1;
        u.z = *(unsigned*)&h2; u.w = *(unsigned*)&h3;
        *(uint4*)(As + r * PADH + q * 8) = u;
    }
}
__device__ __forceinline__ void stage_A64h(__half* As, const __half* src, int row0, int t) {
    for (int task = t; task < 1024; task += 256) {
        int r = task >> 4, q = task & 15;
        int gr = row0 + r;
        __half* dst = As + r * PADH + q * 8;
        if (gr < NN) cp16h(dst, src + (size_t)gr * DD + q * 8);
        else *(uint4*)dst = make_uint4(0, 0, 0, 0);
    }
    CP_COMMIT();
}
__device__ __forceinline__ void cp_Wh(__half* Wh, const __half* src, int t) {
    for (int i = t * 8; i < 128 * PADH; i += 2048) cp16h(Wh + i, src + i);
    CP_COMMIT();
}
__device__ __forceinline__ void gemm_main(float acc[2][4][4], const __half* As,
                                          const __half* Wh, int wm, int wn,
                                          int g, int tg) {
    #pragma unroll
    for (int mt = 0; mt < 2; ++mt)
        #pragma unroll
        for (int nt = 0; nt < 4; ++nt)
            #pragma unroll
            for (int j = 0; j < 4; ++j) acc[mt][nt][j] = 0.f;

    const __half* Ab = As + (wm * 32 + g) * PADH + 2 * tg;
    const __half* Bb = Wh + (wn * 32 + g) * PADH + 2 * tg;

    #pragma unroll
    for (int kk = 0; kk < 8; ++kk) {
        unsigned a[2][4], b[4][2];
        #pragma unroll
        for (int mt = 0; mt < 2; ++mt) {
            const __half* p = Ab + mt * 16 * PADH + kk * 16;
            a[mt][0] = *(const unsigned*)(p);
            a[mt][1] = *(const unsigned*)(p + 8 * PADH);
            a[mt][2] = *(const unsigned*)(p + 8);
            a[mt][3] = *(const unsigned*)(p + 8 * PADH + 8);
        }
        #pragma unroll
        for (int nt = 0; nt < 4; ++nt) {
            const __half* p = Bb + nt * 8 * PADH + kk * 16;
            b[nt][0] = *(const unsigned*)(p);
            b[nt][1] = *(const unsigned*)(p + 8);
        }
        #pragma unroll
        for (int mt = 0; mt < 2; ++mt)
            #pragma unroll
            for (int nt = 0; nt < 4; ++nt)
                mma_f16(acc[mt][nt], a[mt], b[nt]);
    }
}

#define ASZ64 (64 * PADH * 2)
#define WHZ   (128 * PADH * 2)

// ---------------- node projection GEMM (256 thr, M=64, 2 CTAs/SM) --------------
__global__ __launch_bounds__(256, 2)
void k_proj(const float* __restrict__ x, const float* __restrict__ vb) {
    extern __shared__ char smc[];
    __half* As = (__half*)smc;               // [64][PADH]
    __half* Wh = (__half*)(smc + ASZ64);     // [128][PADH]
    const int t = threadIdx.x;
    const int warp = t >> 5, lane = t & 31;
    const int g = lane >> 2, tg = lane & 3;
    const int wm = warp >> 2, wn = warp & 3;
    const int row0 = blockIdx.x * 64;

    cp_Wh(Wh, g_Wt[0], t);
    stage_A64(As, x, row0, t);
    CP_WAIT(0);
    __syncthreads();

    __half* Og[4] = {g_Qh, g_Kh, g_Vh, g_Zh};

    for (int w = 0; w < 4; ++w) {
        float acc[2][4][4];
        gemm_main(acc, As, Wh, wm, wn, g, tg);
        __syncthreads();
        if (w < 3) cp_Wh(Wh, g_Wt[w + 1], t);

        __half* O = Og[w];
        #pragma unroll
        for (int mt = 0; mt < 2; ++mt) {
            int r = row0 + wm * 32 + mt * 16 + g;
            #pragma unroll
            for (int nt = 0; nt < 4; ++nt) {
                int c = wn * 32 + nt * 8 + tg * 2;
                float bv0 = 0.f, bv1 = 0.f;
                if (w == 0) { bv0 = g_eaq[c]; bv1 = g_eaq[c + 1]; }
                else if (w == 1) { bv0 = g_eak[c]; bv1 = g_eak[c + 1]; }
                else if (w == 2) { bv0 = vb[c]; bv1 = vb[c + 1]; }
                if (r < NN)
                    *(__half2*)(O + (size_t)r * DD + c) =
                        __floats2half2_rn(acc[mt][nt][0] + bv0, acc[mt][nt][1] + bv1);
                if (r + 8 < NN)
                    *(__half2*)(O + (size_t)(r + 8) * DD + c) =
                        __floats2half2_rn(acc[mt][nt][2] + bv0, acc[mt][nt][3] + bv1);
            }
        }
        if (w < 3) {
            CP_WAIT(0);
            __syncthreads();
        }
    }
}

// ---------------- edge pass 1 (CSR order, 2-edge unroll): warp per dst ---------
__global__ __launch_bounds__(256, 1)
void k_scores() {
    int n = blockIdx.x * 8 + (threadIdx.x >> 5);
    int lane = threadIdx.x & 31;
    if (n >= NN) return;
    int beg = g_off[n], end = g_off[n + 1];
    if (beg == end) return;
    int h = lane >> 2;

    uint2 ku = *(const uint2*)(g_Kh + (size_t)n * DD + lane * 4);
    float2 k0 = __half22float2(*(__half2*)&ku.x);
    float2 k1 = __half22float2(*(__half2*)&ku.y);

    for (int i = beg; i < end; i += 2) {
        bool two = (i + 1 < end);
        int s0 = g_esrc[i];
        int s1 = two ? g_esrc[i + 1] : s0;
        uint2 qa = *(const uint2*)(g_Qh + (size_t)s0 * DD + lane * 4);
        uint2 qb = *(const uint2*)(g_Qh + (size_t)s1 * DD + lane * 4);
        float2 a0 = __half22float2(*(__half2*)&qa.x);
        float2 a1 = __half22float2(*(__half2*)&qa.y);
        float2 b0 = __half22float2(*(__half2*)&qb.x);
        float2 b1 = __half22float2(*(__half2*)&qb.y);
        float p0 = a0.x * k0.x + a0.y * k0.y + a1.x * k1.x + a1.y * k1.y;
        float p1 = b0.x * k0.x + b0.y * k0.y + b1.x * k1.x + b1.y * k1.y;
        p0 += __shfl_xor_sync(0xffffffffu, p0, 1);
        p1 += __shfl_xor_sync(0xffffffffu, p1, 1);
        p0 += __shfl_xor_sync(0xffffffffu, p0, 2);
        p1 += __shfl_xor_sync(0xffffffffu, p1, 2);
        if ((lane & 3) == 0) {
            float e0 = expf(p0 * 0.25f);
            g_scores[(size_t)i * HH + h] = e0;
            atomicAdd(&g_ssum[s0 * HH + h], e0);
            if (two) {
                float e1 = expf(p1 * 0.25f);
                g_scores[(size_t)(i + 1) * HH + h] = e1;
                atomicAdd(&g_ssum[s1 * HH + h], e1);
            }
        }
    }
}

// ---------------- edge pass 2 (CSR order, 2-edge unroll): warp per dst ---------
__global__ __launch_bounds__(256, 1)
void k_aggr() {
    int n = blockIdx.x * 8 + (threadIdx.x >> 5);
    int lane = threadIdx.x & 31;
    if (n >= NN) return;
    int beg = g_off[n], end = g_off[n + 1];
    int h = lane >> 2;
    uint2 zu = *(const uint2*)(g_Zh + (size_t)n * DD + lane * 4);  // residual f16
    float2 z0 = __half22float2(*(__half2*)&zu.x);
    float2 z1 = __half22float2(*(__half2*)&zu.y);
    float4 acc = make_float4(z0.x, z0.y, z1.x, z1.y);
    for (int i = beg; i < end; i += 2) {
        bool two = (i + 1 < end);
        int s0 = g_esrc[i];
        int s1 = two ? g_esrc[i + 1] : s0;
        float e0 = g_scores[(size_t)i * HH + h];
        float e1 = two ? g_scores[(size_t)(i + 1) * HH + h] : 0.f;
        uint2 va = *(const uint2*)(g_Vh + (size_t)s0 * DD + lane * 4);
        uint2 vb = *(const uint2*)(g_Vh + (size_t)s1 * DD + lane * 4);
        float al0 = __fdividef(e0, g_ssum[s0 * HH + h]);
        float al1 = two ? __fdividef(e1, g_ssum[s1 * HH + h]) : 0.f;
        float2 a0 = __half22float2(*(__half2*)&va.x);
        float2 a1 = __half22float2(*(__half2*)&va.y);
        float2 c0 = __half22float2(*(__half2*)&vb.x);
        float2 c1 = __half22float2(*(__half2*)&vb.y);
        acc.x = fmaf(a0.x, al0, fmaf(c0.x, al1, acc.x));
        acc.y = fmaf(a0.y, al0, fmaf(c0.y, al1, acc.y));
        acc.z = fmaf(a1.x, al0, fmaf(c1.x, al1, acc.z));
        acc.w = fmaf(a1.y, al0, fmaf(c1.y, al1, acc.w));
    }
    __half2 o0 = __floats2half2_rn(acc.x, acc.y);
    __half2 o1 = __floats2half2_rn(acc.z, acc.w);
    uint2 ou;
    ou.x = *(unsigned*)&o0;
    ou.y = *(unsigned*)&o1;
    *(uint2*)(g_Zh + (size_t)n * DD + lane * 4) = ou;
}

// ---------------- fused output MLP (256 thr, M=64, 2 CTAs/SM) ------------------
__global__ __launch_bounds__(256, 2)
void k_out(const float* __restrict__ ob1,
           const float* __restrict__ o_g, const float* __restrict__ o_b,
           const float* __restrict__ o_m, const float* __restrict__ o_v,
           const float* __restrict__ ob2, float* __restrict__ out) {
    extern __shared__ char smc[];
    __half* As  = (__half*)smc;                    // [64][PADH]
    __half* Wh  = (__half*)(smc + ASZ64);          // [128][PADH]
    float*  bnS = (float*)(smc + ASZ64 + WHZ);     // sc[128], sh[128], b1[128]
    const int t = threadIdx.x;
    const int warp = t >> 5, lane = t & 31;
    const int g = lane >> 2, tg = lane & 3;
    const int wm = warp >> 2, wn = warp & 3;
    const int row0 = blockIdx.x * 64;

    cp_Wh(Wh, g_Wt[4], t);
    stage_A64h(As, g_Zh, row0, t);
    if (t < 128) {
        float sc = o_g[t] * rsqrtf(o_v[t] + 1e-5f);
        bnS[t]       = sc;
        bnS[128 + t] = o_b[t] - o_m[t] * sc;
        bnS[256 + t] = ob1[t];
    }
    CP_WAIT(0);
    __syncthreads();

    float acc[2][4][4];
    gemm_main(acc, As, Wh, wm, wn, g, tg);
    __syncthreads();
    cp_Wh(Wh, g_Wt[5], t);

    #pragma unroll
    for (int mt = 0; mt < 2; ++mt) {
        int rl = wm * 32 + mt * 16 + g;
        #pragma unroll
        for (int nt = 0; nt < 4; ++nt) {
            int c = wn * 32 + nt * 8 + tg * 2;
            float sc0 = bnS[c],       sc1 = bnS[c + 1];
            float sh0 = bnS[128 + c], sh1 = bnS[129 + c];
            float b10 = bnS[256 + c], b11 = bnS[257 + c];
            float y0 = (acc[mt][nt][0] + b10) * sc0 + sh0;
            float y1 = (acc[mt][nt][1] + b11) * sc1 + sh1;
            float y2 = (acc[mt][nt][2] + b10) * sc0 + sh0;
            float y3 = (acc[mt][nt][3] + b11) * sc1 + sh1;
            y0 = (y0 > 0.f) ? y0 : 0.01f * y0;
            y1 = (y1 > 0.f) ? y1 : 0.01f * y1;
            y2 = (y2 > 0.f) ? y2 : 0.01f * y2;
            y3 = (y3 > 0.f) ? y3 : 0.01f * y3;
            *(__half2*)(As + rl * PADH + c)       = __floats2half2_rn(y0, y1);
            *(__half2*)(As + (rl + 8) * PADH + c) = __floats2half2_rn(y2, y3);
        }
    }
    CP_WAIT(0);
    __syncthreads();

    gemm_main(acc, As, Wh, wm, wn, g, tg);

    #pragma unroll
    for (int mt = 0; mt < 2; ++mt) {
        int r = row0 + wm * 32 + mt * 16 + g;
        #pragma unroll
        for (int nt = 0; nt < 4; ++nt) {
            int c = wn * 32 + nt * 8 + tg * 2;
            float b20 = ob2[c], b21 = ob2[c + 1];
            if (r < NN)
                *(float2*)(out + (size_t)r * DD + c) =
                    make_float2(acc[mt][nt][0] + b20, acc[mt][nt][1] + b21);
            if (r + 8 < NN)
                *(float2*)(out + (size_t)(r + 8) * DD + c) =
                    make_float2(acc[mt][nt][2] + b20, acc[mt][nt][3] + b21);
        }
    }
}

// ---------------- launch (fork-join graph: CSR branch ∥ GEMM branch) -----------
extern "C" void kernel_launch(void* const* d_in, const int* in_sizes, int n_in,
                              void* d_out, int out_size) {
    const float* x    = (const float*)d_in[0];
    const void*  ei   = d_in[1];
    const float* nt   = (const float*)d_in[2];
    const float* et   = (const float*)d_in[3];
    const float* mW1  = (const float*)d_in[4];
    const float* mb1  = (const float*)d_in[5];
    const float* m_g  = (const float*)d_in[6];
    const float* m_b  = (const float*)d_in[7];
    const float* m_m  = (const float*)d_in[8];
    const float* m_v  = (const float*)d_in[9];
    const float* mW2  = (const float*)d_in[10];
    const float* mb2  = (const float*)d_in[11];
    const float* resW = (const float*)d_in[12];
    const float* qW   = (const float*)d_in[13];
    const float* qb   = (const float*)d_in[14];
    const float* kW   = (const float*)d_in[15];
    const float* kb   = (const float*)d_in[16];
    const float* vW   = (const float*)d_in[17];
    const float* vb   = (const float*)d_in[18];
    const float* oW1  = (const float*)d_in[19];
    const float* ob1  = (const float*)d_in[20];
    const float* o_g  = (const float*)d_in[21];
    const float* o_b  = (const float*)d_in[22];
    const float* o_m  = (const float*)d_in[23];
    const float* o_v  = (const float*)d_in[24];
    const float* oW2  = (const float*)d_in[25];
    const float* ob2  = (const float*)d_in[26];
    float* out = (float*)d_out;

    const int SMEM_P = ASZ64 + WHZ;
    const int SMEM_O = SMEM_P + 3 * 128 * (int)sizeof(float);
    cudaFuncSetAttribute(k_proj, cudaFuncAttributeMaxDynamicSharedMemorySize, SMEM_P);
    cudaFuncSetAttribute(k_out,  cudaFuncAttributeMaxDynamicSharedMemorySize, SMEM_O);

    // one-time side stream + events (host-side resources; no device allocation)
    static cudaStream_t sB = 0;
    static cudaEvent_t evFork = 0, evJoin = 0;
    static bool init_ok = false;
    static bool tried = false;
    if (!tried) {
        tried = true;
        init_ok = (cudaStreamCreateWithFlags(&sB, cudaStreamNonBlocking) == cudaSuccess) &&
                  (cudaEventCreateWithFlags(&evFork, cudaEventDisableTiming) == cudaSuccess) &&
                  (cudaEventCreateWithFlags(&evJoin, cudaEventDisableTiming) == cudaSuccess);
    }

    if (init_ok) {
        // fork: CSR branch on sB
        cudaEventRecord(evFork, 0);
        cudaStreamWaitEvent(sB, evFork, 0);
        k_detect<<<(NN + 255) / 256, 256, 0, sB>>>((const int*)ei);
        k_cvt<<<(EE + 255) / 256, 256, 0, sB>>>(ei);
        k_scan1<<<NB, 1024, 0, sB>>>();
        k_scan2<<<1, 32, 0, sB>>>();
        k_scan3<<<(NN + 255) / 256, 256, 0, sB>>>();
        k_scatter<<<(EE + 255) / 256, 256, 0, sB>>>();
        cudaEventRecord(evJoin, sB);

        // GEMM branch on default stream
        k_wt<<<6, 256>>>(qW, kW, vW, resW, oW1, oW2);
        k_ea<<<1, 128>>>(nt, et, mW1, mb1, m_g, m_b, m_m, m_v, mW2, mb2, qW, qb, kW, kb);
        k_proj<<<(NN + 63) / 64, 256, SMEM_P>>>(x, vb);

        // join
        cudaStreamWaitEvent(0, evJoin, 0);
    } else {
        // sequential fallback
        k_wt<<<6, 256>>>(qW, kW, vW, resW, oW1, oW2);
        k_ea<<<1, 128>>>(nt, et, mW1, mb1, m_g, m_b, m_m, m_v, mW2, mb2, qW, qb, kW, kb);
        k_detect<<<(NN + 255) / 256, 256>>>((const int*)ei);
        k_proj<<<(NN + 63) / 64, 256, SMEM_P>>>(x, vb);
        k_cvt<<<(EE + 255) / 256, 256>>>(ei);
        k_scan1<<<NB, 1024>>>();
        k_scan2<<<1, 32>>>();
        k_scan3<<<(NN + 255) / 256, 256>>>();
        k_scatter<<<(EE + 255) / 256, 256>>>();
    }

    k_scores<<<(NN + 7) / 8, 256>>>();
    k_aggr<<<(NN + 7) / 8, 256>>>();
    k_out<<<(NN + 63) / 64, 256, SMEM_O>>>(ob1, o_g, o_b, o_m, o_v, ob2, out);
}